// round 1
// baseline (speedup 1.0000x reference)
#include <cuda_runtime.h>
#include <cstdint>

// ---------------- problem constants ----------------
#define N_TOK 8192      // B*S = 2*4096
#define H     1024
#define E     8
#define IE    512
#define F2    1024      // 2*IE
#define VOCAB 32000

// ---------------- scratch (device globals; no allocation allowed) ----------
__device__ int   g_expert_ids[N_TOK];
__device__ int   g_counts[E];
__device__ int   g_offsets[E + 1];
__device__ int   g_cursor[E];
__device__ int   g_sorted[N_TOK];
__device__ int   g_tile_expert[96];
__device__ int   g_tile_mstart[96];
__device__ int   g_num_tiles;
__device__ float g_inter[(size_t)N_TOK * IE];   // 16 MB, expert-sorted order

// ---------------- packed f32x2 helpers (FFMA2 path on sm_103a) -------------
__device__ __forceinline__ unsigned long long pack2(float a) {
    unsigned long long r;
    unsigned u = __float_as_uint(a);
    asm("mov.b64 %0, {%1, %1};" : "=l"(r) : "r"(u));
    return r;
}
__device__ __forceinline__ void ffma2(unsigned long long& d,
                                      unsigned long long a,
                                      unsigned long long b) {
    asm("fma.rn.f32x2 %0, %1, %2, %0;" : "+l"(d) : "l"(a), "l"(b));
}
__device__ __forceinline__ float lo32(unsigned long long v) {
    return __uint_as_float((unsigned)v);
}
__device__ __forceinline__ float hi32(unsigned long long v) {
    return __uint_as_float((unsigned)(v >> 32));
}

// ---------------- 0: init ----------------
__global__ void k_init() {
    int t = threadIdx.x;
    if (t < E) g_counts[t] = 0;
}

// ---------------- 1: router (warp per token) ----------------
__global__ void k_router(const float* __restrict__ mu,
                         const int* __restrict__ tok,
                         const float* __restrict__ w) {
    __shared__ float ws[E * H];  // 32 KB router weights
    int tid = threadIdx.x;
    for (int i = tid; i < E * H; i += 256) ws[i] = w[i];
    __syncthreads();

    int warp = tid >> 5, lane = tid & 31;
    int n = blockIdx.x * 8 + warp;
    const float* mrow = mu + (size_t)n * H;

    float acc[E];
#pragma unroll
    for (int e = 0; e < E; e++) acc[e] = 0.f;

    for (int h = lane; h < H; h += 32) {
        float m = mrow[h];
#pragma unroll
        for (int e = 0; e < E; e++) acc[e] += m * ws[e * H + h];
    }
#pragma unroll
    for (int off = 16; off > 0; off >>= 1) {
#pragma unroll
        for (int e = 0; e < E; e++)
            acc[e] += __shfl_down_sync(0xffffffffu, acc[e], off);
    }
    if (lane == 0) {
        int id = tok[n];
        if (id < 0) id = 0;
        if (id >= VOCAB) id = VOCAB - 1;
        int base = id & (E - 1);
        float best = -1e30f;
        int be = 0;
#pragma unroll
        for (int e = 0; e < E; e++) {
            float v = acc[e] + (e == base ? 10.0f : 0.0f);
            if (v > best) { best = v; be = e; }   // first-max like jnp.argmax
        }
        g_expert_ids[n] = be;
        atomicAdd(&g_counts[be], 1);
    }
}

// ---------------- 2: plan (prefix sums + tile table) ----------------
__global__ void k_plan() {
    int off = 0;
    for (int e = 0; e < E; e++) {
        g_offsets[e] = off;
        g_cursor[e]  = off;
        off += g_counts[e];
    }
    g_offsets[E] = off;
    int t = 0;
    for (int e = 0; e < E; e++) {
        int cnt = g_counts[e];
        for (int ms = 0; ms < cnt; ms += 128) {
            g_tile_expert[t] = e;
            g_tile_mstart[t] = ms;
            t++;
        }
    }
    g_num_tiles = t;
}

// ---------------- 3: scatter tokens into expert order ----------------
__global__ void k_scatter() {
    int n = blockIdx.x * 256 + threadIdx.x;
    if (n < N_TOK) {
        int e = g_expert_ids[n];
        int p = atomicAdd(&g_cursor[e], 1);
        g_sorted[p] = n;
    }
}

// ---------------- GEMM tile config ----------------
#define BM  128
#define BN  64
#define BK  16
#define BMP 132   // padded A row (multiple of 4 for float4 compute loads)

// ---------------- 4: GEMM1 fused: inter = silu(x@Wg) * (x@Wu) --------------
__global__ __launch_bounds__(256, 2)
void k_gemm1(const float* __restrict__ x, const float* __restrict__ gup) {
    int t = blockIdx.x;
    if (t >= g_num_tiles) return;
    int e  = g_tile_expert[t];
    int m0 = g_offsets[e] + g_tile_mstart[t];
    int rows = g_offsets[e + 1] - m0;
    if (rows > BM) rows = BM;
    int n0 = blockIdx.y * BN;
    const float* W = gup + (size_t)e * H * F2;

    __shared__ __align__(16) float sA[BK * BMP];
    __shared__ __align__(16) float sBg[BK * BN];
    __shared__ __align__(16) float sBu[BK * BN];
    __shared__ int sRow[BM];

    int tid = threadIdx.x;
    for (int i = tid; i < BM; i += 256)
        sRow[i] = (i < rows) ? g_sorted[m0 + i] : -1;
    __syncthreads();

    int tr = tid >> 4;   // 0..15  -> rows tr*8 .. tr*8+7
    int tc = tid & 15;   // 0..15  -> cols tc*4 .. tc*4+3

    unsigned long long accg[8][2], accu[8][2];
#pragma unroll
    for (int i = 0; i < 8; i++) {
        accg[i][0] = accg[i][1] = 0ull;
        accu[i][0] = accu[i][1] = 0ull;
    }

    for (int k0 = 0; k0 < H; k0 += BK) {
        // A tile (gathered rows)
#pragma unroll
        for (int i = tid; i < BM * BK; i += 256) {
            int m = i >> 4, k = i & 15;
            int r = sRow[m];
            sA[k * BMP + m] = (r >= 0) ? x[(size_t)r * H + k0 + k] : 0.f;
        }
        // B tiles: gate cols [n0,n0+64), up cols [512+n0, 512+n0+64)
#pragma unroll
        for (int i = tid; i < BK * BN; i += 256) {
            int k = i >> 6, n = i & 63;
            const float* wp = W + (size_t)(k0 + k) * F2 + n0 + n;
            sBg[k * BN + n] = wp[0];
            sBu[k * BN + n] = wp[IE];
        }
        __syncthreads();

#pragma unroll
        for (int k = 0; k < BK; k++) {
            const float* ap = &sA[k * BMP + tr * 8];
            float4 av0 = *(const float4*)(ap);
            float4 av1 = *(const float4*)(ap + 4);
            unsigned long long a2[8];
            a2[0] = pack2(av0.x); a2[1] = pack2(av0.y);
            a2[2] = pack2(av0.z); a2[3] = pack2(av0.w);
            a2[4] = pack2(av1.x); a2[5] = pack2(av1.y);
            a2[6] = pack2(av1.z); a2[7] = pack2(av1.w);
            const unsigned long long* bg =
                (const unsigned long long*)&sBg[k * BN + tc * 4];
            const unsigned long long* bu =
                (const unsigned long long*)&sBu[k * BN + tc * 4];
            unsigned long long bg0 = bg[0], bg1 = bg[1];
            unsigned long long bu0 = bu[0], bu1 = bu[1];
#pragma unroll
            for (int i = 0; i < 8; i++) {
                ffma2(accg[i][0], a2[i], bg0);
                ffma2(accg[i][1], a2[i], bg1);
                ffma2(accu[i][0], a2[i], bu0);
                ffma2(accu[i][1], a2[i], bu1);
            }
        }
        __syncthreads();
    }

    // epilogue: silu(gate) * up  -> g_inter (sorted order)
    int mb = tr * 8;
#pragma unroll
    for (int i = 0; i < 8; i++) {
        int m = mb + i;
        if (m < rows) {
            float* op = &g_inter[(size_t)(m0 + m) * IE + n0 + tc * 4];
#pragma unroll
            for (int jp = 0; jp < 2; jp++) {
                float gx = lo32(accg[i][jp]), gy = hi32(accg[i][jp]);
                float ux = lo32(accu[i][jp]), uy = hi32(accu[i][jp]);
                op[jp * 2 + 0] = gx / (1.f + __expf(-gx)) * ux;
                op[jp * 2 + 1] = gy / (1.f + __expf(-gy)) * uy;
            }
        }
    }
}

// ---------------- 5: GEMM2: out = inter @ down[e], scatter back ------------
__global__ __launch_bounds__(256, 2)
void k_gemm2(const float* __restrict__ dwn, float* __restrict__ out) {
    int t = blockIdx.x;
    if (t >= g_num_tiles) return;
    int e  = g_tile_expert[t];
    int m0 = g_offsets[e] + g_tile_mstart[t];
    int rows = g_offsets[e + 1] - m0;
    if (rows > BM) rows = BM;
    int n0 = blockIdx.y * BN;
    const float* W = dwn + (size_t)e * IE * H;

    __shared__ __align__(16) float sA[BK * BMP];
    __shared__ __align__(16) float sB[BK * BN];
    __shared__ int sRow[BM];

    int tid = threadIdx.x;
    for (int i = tid; i < BM; i += 256)
        sRow[i] = (i < rows) ? g_sorted[m0 + i] : -1;
    __syncthreads();

    int tr = tid >> 4;
    int tc = tid & 15;

    unsigned long long acc[8][2];
#pragma unroll
    for (int i = 0; i < 8; i++) acc[i][0] = acc[i][1] = 0ull;

    for (int k0 = 0; k0 < IE; k0 += BK) {
#pragma unroll
        for (int i = tid; i < BM * BK; i += 256) {
            int m = i >> 4, k = i & 15;
            sA[k * BMP + m] =
                (m < rows) ? g_inter[(size_t)(m0 + m) * IE + k0 + k] : 0.f;
        }
#pragma unroll
        for (int i = tid; i < BK * BN; i += 256) {
            int k = i >> 6, n = i & 63;
            sB[k * BN + n] = W[(size_t)(k0 + k) * H + n0 + n];
        }
        __syncthreads();

#pragma unroll
        for (int k = 0; k < BK; k++) {
            const float* ap = &sA[k * BMP + tr * 8];
            float4 av0 = *(const float4*)(ap);
            float4 av1 = *(const float4*)(ap + 4);
            unsigned long long a2[8];
            a2[0] = pack2(av0.x); a2[1] = pack2(av0.y);
            a2[2] = pack2(av0.z); a2[3] = pack2(av0.w);
            a2[4] = pack2(av1.x); a2[5] = pack2(av1.y);
            a2[6] = pack2(av1.z); a2[7] = pack2(av1.w);
            const unsigned long long* bp =
                (const unsigned long long*)&sB[k * BN + tc * 4];
            unsigned long long b0 = bp[0], b1 = bp[1];
#pragma unroll
            for (int i = 0; i < 8; i++) {
                ffma2(acc[i][0], a2[i], b0);
                ffma2(acc[i][1], a2[i], b1);
            }
        }
        __syncthreads();
    }

    int mb = tr * 8;
#pragma unroll
    for (int i = 0; i < 8; i++) {
        int m = mb + i;
        if (m < rows) {
            int token = sRow[m];
            float* op = out + (size_t)token * H + n0 + tc * 4;
            op[0] = lo32(acc[i][0]);
            op[1] = hi32(acc[i][0]);
            op[2] = lo32(acc[i][1]);
            op[3] = hi32(acc[i][1]);
        }
    }
}

// ---------------- launch ----------------
extern "C" void kernel_launch(void* const* d_in, const int* in_sizes, int n_in,
                              void* d_out, int out_size) {
    const float* hs  = (const float*)d_in[0];   // hidden_states (2,4096,1024)
    const int*   tok = (const int*)d_in[1];     // token_ids     (2,4096)
    const float* mu  = (const float*)d_in[2];   // mu            (2,4096,1024)
    const float* gup = (const float*)d_in[3];   // gate_up_proj  (8,1024,1024)
    const float* dwn = (const float*)d_in[4];   // down_proj     (8,512,1024)
    const float* rw  = (const float*)d_in[5];   // mu_router_w   (8,1024)
    float* out = (float*)d_out;

    (void)in_sizes; (void)n_in; (void)out_size;

    k_init<<<1, 32>>>();
    k_router<<<N_TOK / 8, 256>>>(mu, tok, rw);
    k_plan<<<1, 1>>>();
    k_scatter<<<N_TOK / 256, 256>>>();
    // max tiles: ceil(8192/128) + (E-1) partials = 71 -> grid 72 with early exit
    k_gemm1<<<dim3(72, IE / BN), 256>>>(hs, gup);
    k_gemm2<<<dim3(72, H / BN), 256>>>(dwn, out);
}

// round 3
// speedup vs baseline: 2.1187x; 2.1187x over previous
#include <cuda_runtime.h>
#include <cuda_bf16.h>
#include <cstdint>

// ---------------- problem constants ----------------
#define N_TOK 8192
#define H     1024
#define E     8
#define IE    512
#define F2    1024
#define VOCAB 32000

// ---------------- scratch ----------------
__device__ int g_expert_ids[N_TOK];
__device__ int g_counts[E];
__device__ int g_offsets[E + 1];
__device__ int g_cursor[E];
__device__ int g_sorted[N_TOK];
__device__ int g_tile_expert[96];
__device__ int g_tile_mstart[96];
__device__ int g_num_tiles;

__device__ __nv_bfloat16 g_x_hi[(size_t)N_TOK * H];
__device__ __nv_bfloat16 g_x_lo[(size_t)N_TOK * H];
__device__ __nv_bfloat16 g_gup_hi[(size_t)E * H * F2];   // [E][H][F2] (K-major rows)
__device__ __nv_bfloat16 g_gup_lo[(size_t)E * H * F2];
__device__ __nv_bfloat16 g_dwn_hi[(size_t)E * IE * H];   // [E][IE][H]
__device__ __nv_bfloat16 g_dwn_lo[(size_t)E * IE * H];
__device__ __nv_bfloat16 g_inter_hi[(size_t)N_TOK * IE]; // sorted order
__device__ __nv_bfloat16 g_inter_lo[(size_t)N_TOK * IE];

// ---------------- PTX helpers ----------------
__device__ __forceinline__ uint32_t s2u(const void* p) {
    uint32_t a;
    asm("{ .reg .u64 t; cvta.to.shared.u64 t, %1; cvt.u32.u64 %0, t; }"
        : "=r"(a) : "l"(p));
    return a;
}
__device__ __forceinline__ void cp16(uint32_t dst, const void* src, int sz) {
    asm volatile("cp.async.ca.shared.global [%0], [%1], 16, %2;"
                 :: "r"(dst), "l"(src), "r"(sz) : "memory");
}
__device__ __forceinline__ void cp_commit() {
    asm volatile("cp.async.commit_group;" ::: "memory");
}
__device__ __forceinline__ void cp_wait1() {
    asm volatile("cp.async.wait_group 1;" ::: "memory");
}
__device__ __forceinline__ void ldmx4(uint32_t* r, uint32_t a) {
    asm volatile("ldmatrix.sync.aligned.m8n8.x4.shared.b16 {%0,%1,%2,%3}, [%4];"
                 : "=r"(r[0]), "=r"(r[1]), "=r"(r[2]), "=r"(r[3]) : "r"(a));
}
__device__ __forceinline__ void ldmx4t(uint32_t* r, uint32_t a) {
    asm volatile("ldmatrix.sync.aligned.m8n8.x4.trans.shared.b16 {%0,%1,%2,%3}, [%4];"
                 : "=r"(r[0]), "=r"(r[1]), "=r"(r[2]), "=r"(r[3]) : "r"(a));
}
__device__ __forceinline__ void mma16816(float* d, const uint32_t* a,
                                         const uint32_t* b) {
    asm volatile(
        "mma.sync.aligned.m16n8k16.row.col.f32.bf16.bf16.f32 "
        "{%0,%1,%2,%3}, {%4,%5,%6,%7}, {%8,%9}, {%0,%1,%2,%3};"
        : "+f"(d[0]), "+f"(d[1]), "+f"(d[2]), "+f"(d[3])
        : "r"(a[0]), "r"(a[1]), "r"(a[2]), "r"(a[3]), "r"(b[0]), "r"(b[1]));
}

// ---------------- smem layout ----------------
// per stage: Ah[128][40] Al[128][40] Bh[32][136] Bl[32][136]  (bf16)
#define A_ROWB 80      // 40 bf16
#define B_ROWB 272     // 136 bf16
#define OFF_AH 0
#define OFF_AL 10240
#define OFF_BH 20480
#define OFF_BL 29184
#define STG    37888
#define STAGE_BASE 512
#define SMEM_TOT (STAGE_BASE + 3 * STG)

__device__ __forceinline__ uint32_t a_addr(uint32_t base, int lane, int mbase,
                                           int k16) {
    int row = mbase + (lane & 15);
    int kcol = k16 * 16 + ((lane >> 4) << 3);
    return base + row * A_ROWB + kcol * 2;
}
__device__ __forceinline__ uint32_t b_addr(uint32_t base, int lane, int nbase,
                                           int k16) {
    int krow = k16 * 16 + (lane & 15);
    int ncol = nbase + ((lane >> 4) << 3);
    return base + krow * B_ROWB + ncol * 2;
}

// one k16 step: 48 HMMA, 12 ldmatrix.x4
__device__ __forceinline__ void compute_k16(uint32_t sb, int lane, int warpM,
                                            int p0, int p1, int k16,
                                            float acc[4][4][4]) {
    uint32_t ah[4][4], al[4][4], bh[2][4], bl[2][4];
#pragma unroll
    for (int i = 0; i < 4; i++) {
        ldmx4(ah[i], a_addr(sb + OFF_AH, lane, warpM * 64 + i * 16, k16));
        ldmx4(al[i], a_addr(sb + OFF_AL, lane, warpM * 64 + i * 16, k16));
    }
    ldmx4t(bh[0], b_addr(sb + OFF_BH, lane, p0, k16));
    ldmx4t(bh[1], b_addr(sb + OFF_BH, lane, p1, k16));
    ldmx4t(bl[0], b_addr(sb + OFF_BL, lane, p0, k16));
    ldmx4t(bl[1], b_addr(sb + OFF_BL, lane, p1, k16));
#pragma unroll
    for (int i = 0; i < 4; i++) {
#pragma unroll
        for (int j = 0; j < 4; j++) {
            const uint32_t* bhp = &bh[j >> 1][(j & 1) * 2];
            const uint32_t* blp = &bl[j >> 1][(j & 1) * 2];
            mma16816(acc[i][j], ah[i], bhp);
            mma16816(acc[i][j], ah[i], blp);
            mma16816(acc[i][j], al[i], bhp);
        }
    }
}

// ---------------- small kernels ----------------
__global__ void k_init() {
    if (threadIdx.x < E) g_counts[threadIdx.x] = 0;
}

__global__ void k_router(const float* __restrict__ mu, const int* __restrict__ tok,
                         const float* __restrict__ w) {
    __shared__ float ws[E * H];
    int tid = threadIdx.x;
    for (int i = tid; i < E * H; i += 256) ws[i] = w[i];
    __syncthreads();
    int warp = tid >> 5, lane = tid & 31;
    int n = blockIdx.x * 8 + warp;
    const float* mrow = mu + (size_t)n * H;
    float acc[E];
#pragma unroll
    for (int e = 0; e < E; e++) acc[e] = 0.f;
    for (int h = lane; h < H; h += 32) {
        float m = mrow[h];
#pragma unroll
        for (int e = 0; e < E; e++) acc[e] += m * ws[e * H + h];
    }
#pragma unroll
    for (int off = 16; off > 0; off >>= 1)
#pragma unroll
        for (int e = 0; e < E; e++)
            acc[e] += __shfl_down_sync(0xffffffffu, acc[e], off);
    if (lane == 0) {
        int id = tok[n];
        if (id < 0) id = 0;
        if (id >= VOCAB) id = VOCAB - 1;
        int base = id & (E - 1);
        float best = -1e30f;
        int be = 0;
#pragma unroll
        for (int e = 0; e < E; e++) {
            float v = acc[e] + (e == base ? 10.0f : 0.0f);
            if (v > best) { best = v; be = e; }
        }
        g_expert_ids[n] = be;
        atomicAdd(&g_counts[be], 1);
    }
}

__global__ void k_plan() {
    int off = 0;
    for (int e = 0; e < E; e++) {
        g_offsets[e] = off;
        g_cursor[e] = off;
        off += g_counts[e];
    }
    g_offsets[E] = off;
    int t = 0;
    for (int e = 0; e < E; e++) {
        int cnt = g_counts[e];
        for (int ms = 0; ms < cnt; ms += 128) {
            g_tile_expert[t] = e;
            g_tile_mstart[t] = ms;
            t++;
        }
    }
    g_num_tiles = t;
}

__global__ void k_scatter() {
    int n = blockIdx.x * 256 + threadIdx.x;
    if (n < N_TOK) {
        int e = g_expert_ids[n];
        int p = atomicAdd(&g_cursor[e], 1);
        g_sorted[p] = n;
    }
}

// elementwise fp32 -> bf16 hi/lo split (n4 = count/4)
__global__ void k_split(const float* __restrict__ in,
                        __nv_bfloat16* __restrict__ oh,
                        __nv_bfloat16* __restrict__ ol, int n4) {
    int i = blockIdx.x * 256 + threadIdx.x;
    if (i >= n4) return;
    float4 v = ((const float4*)in)[i];
    float vs[4] = {v.x, v.y, v.z, v.w};
    ushort hh[4], ll[4];
#pragma unroll
    for (int j = 0; j < 4; j++) {
        __nv_bfloat16 h = __float2bfloat16(vs[j]);
        __nv_bfloat16 l = __float2bfloat16(vs[j] - __bfloat162float(h));
        hh[j] = __bfloat16_as_ushort(h);
        ll[j] = __bfloat16_as_ushort(l);
    }
    uint2 ph = make_uint2((uint32_t)hh[0] | ((uint32_t)hh[1] << 16),
                          (uint32_t)hh[2] | ((uint32_t)hh[3] << 16));
    uint2 pl = make_uint2((uint32_t)ll[0] | ((uint32_t)ll[1] << 16),
                          (uint32_t)ll[2] | ((uint32_t)ll[3] << 16));
    ((uint2*)oh)[i] = ph;
    ((uint2*)ol)[i] = pl;
}

// ---------------- GEMM1: inter = silu(x@Wg)*(x@Wu) ----------------
__device__ __forceinline__ void g1_load(uint32_t sb, const int* sRow,
                                        const __nv_bfloat16* wh,
                                        const __nv_bfloat16* wl,
                                        int k0, int n0g, int tid) {
#pragma unroll
    for (int q = 0; q < 2; q++) {
        int t = tid * 2 + q;  // 0..511
        // A: row = t>>2 (0..127), chunk c = t&3 (8 bf16 each)
        int row = t >> 2, c = t & 3;
        int r = sRow[row];
        int sz = (r >= 0) ? 16 : 0;
        size_t so = (size_t)(r >= 0 ? r : 0) * H + k0 + c * 8;
        cp16(sb + OFF_AH + row * A_ROWB + c * 16, g_x_hi + so, sz);
        cp16(sb + OFF_AL + row * A_ROWB + c * 16, g_x_lo + so, sz);
        // B: krow = t>>4 (0..31), chunk c2 = t&15
        int kr = t >> 4, c2 = t & 15;
        int col = (c2 < 8) ? (n0g + c2 * 8) : (IE + n0g + (c2 - 8) * 8);
        size_t wo = (size_t)(k0 + kr) * F2 + col;
        cp16(sb + OFF_BH + kr * B_ROWB + c2 * 16, wh + wo, 16);
        cp16(sb + OFF_BL + kr * B_ROWB + c2 * 16, wl + wo, 16);
    }
}

__global__ __launch_bounds__(256) void k_gemm1_mma() {
    int t = blockIdx.x;
    if (t >= g_num_tiles) return;
    int e = g_tile_expert[t];
    int m0 = g_offsets[e] + g_tile_mstart[t];
    int rows = g_offsets[e + 1] - m0;
    if (rows > 128) rows = 128;
    int n0g = blockIdx.y * 64;

    extern __shared__ char smraw[];
    int* sRow = (int*)smraw;
    uint32_t sb = s2u(smraw) + STAGE_BASE;
    int tid = threadIdx.x;
    if (tid < 128) sRow[tid] = (tid < rows) ? g_sorted[m0 + tid] : -1;
    __syncthreads();

    const __nv_bfloat16* wh = g_gup_hi + (size_t)e * H * F2;
    const __nv_bfloat16* wl = g_gup_lo + (size_t)e * H * F2;

    g1_load(sb + 0 * STG, sRow, wh, wl, 0, n0g, tid);
    cp_commit();
    g1_load(sb + 1 * STG, sRow, wh, wl, 32, n0g, tid);
    cp_commit();

    float acc[4][4][4];
#pragma unroll
    for (int i = 0; i < 4; i++)
#pragma unroll
        for (int j = 0; j < 4; j++)
#pragma unroll
            for (int r = 0; r < 4; r++) acc[i][j][r] = 0.f;

    int lane = tid & 31, w = tid >> 5;
    int warpM = w >> 2, warpN = w & 3;
    int p0 = warpN * 16, p1 = 64 + warpN * 16;

    const int NK = H / 32;  // 32
    for (int ki = 0; ki < NK; ki++) {
        cp_wait1();
        __syncthreads();
        if (ki + 2 < NK)
            g1_load(sb + ((ki + 2) % 3) * STG, sRow, wh, wl, (ki + 2) * 32, n0g, tid);
        cp_commit();
        uint32_t stb = sb + (ki % 3) * STG;
        compute_k16(stb, lane, warpM, p0, p1, 0, acc);
        compute_k16(stb, lane, warpM, p0, p1, 1, acc);
    }

    // epilogue: j=0,1 gate; j+2 up (same cols)
#pragma unroll
    for (int i = 0; i < 4; i++) {
        int r0 = warpM * 64 + i * 16 + (lane >> 2);
#pragma unroll
        for (int j = 0; j < 2; j++) {
            int col = n0g + warpN * 16 + j * 8 + (lane & 3) * 2;
#pragma unroll
            for (int hfa = 0; hfa < 2; hfa++) {
                int m = r0 + hfa * 8;
                if (m < rows) {
                    float g0 = acc[i][j][hfa * 2 + 0];
                    float g1 = acc[i][j][hfa * 2 + 1];
                    float u0 = acc[i][j + 2][hfa * 2 + 0];
                    float u1 = acc[i][j + 2][hfa * 2 + 1];
                    float v0 = g0 / (1.f + __expf(-g0)) * u0;
                    float v1 = g1 / (1.f + __expf(-g1)) * u1;
                    __nv_bfloat16 h0 = __float2bfloat16(v0);
                    __nv_bfloat16 h1 = __float2bfloat16(v1);
                    __nv_bfloat16 l0 = __float2bfloat16(v0 - __bfloat162float(h0));
                    __nv_bfloat16 l1 = __float2bfloat16(v1 - __bfloat162float(h1));
                    size_t o = ((size_t)(m0 + m) * IE + col) >> 1;
                    ((uint32_t*)g_inter_hi)[o] =
                        (uint32_t)__bfloat16_as_ushort(h0) |
                        ((uint32_t)__bfloat16_as_ushort(h1) << 16);
                    ((uint32_t*)g_inter_lo)[o] =
                        (uint32_t)__bfloat16_as_ushort(l0) |
                        ((uint32_t)__bfloat16_as_ushort(l1) << 16);
                }
            }
        }
    }
}

// ---------------- GEMM2: out = inter @ down[e], scatter ----------------
__device__ __forceinline__ void g2_load(uint32_t sb, int m0, int rows,
                                        const __nv_bfloat16* wh,
                                        const __nv_bfloat16* wl,
                                        int k0, int n0, int tid) {
#pragma unroll
    for (int q = 0; q < 2; q++) {
        int t = tid * 2 + q;
        int row = t >> 2, c = t & 3;
        int sz = (row < rows) ? 16 : 0;
        size_t so = (size_t)(m0 + (row < rows ? row : 0)) * IE + k0 + c * 8;
        cp16(sb + OFF_AH + row * A_ROWB + c * 16, g_inter_hi + so, sz);
        cp16(sb + OFF_AL + row * A_ROWB + c * 16, g_inter_lo + so, sz);
        int kr = t >> 4, c2 = t & 15;
        size_t wo = (size_t)(k0 + kr) * H + n0 + c2 * 8;
        cp16(sb + OFF_BH + kr * B_ROWB + c2 * 16, wh + wo, 16);
        cp16(sb + OFF_BL + kr * B_ROWB + c2 * 16, wl + wo, 16);
    }
}

__global__ __launch_bounds__(256) void k_gemm2_mma(float* __restrict__ out) {
    int t = blockIdx.x;
    if (t >= g_num_tiles) return;
    int e = g_tile_expert[t];
    int m0 = g_offsets[e] + g_tile_mstart[t];
    int rows = g_offsets[e + 1] - m0;
    if (rows > 128) rows = 128;
    int n0 = blockIdx.y * 128;

    extern __shared__ char smraw[];
    int* sRow = (int*)smraw;
    uint32_t sb = s2u(smraw) + STAGE_BASE;
    int tid = threadIdx.x;
    if (tid < 128) sRow[tid] = (tid < rows) ? g_sorted[m0 + tid] : -1;
    __syncthreads();

    const __nv_bfloat16* wh = g_dwn_hi + (size_t)e * IE * H;
    const __nv_bfloat16* wl = g_dwn_lo + (size_t)e * IE * H;

    g2_load(sb + 0 * STG, m0, rows, wh, wl, 0, n0, tid);
    cp_commit();
    g2_load(sb + 1 * STG, m0, rows, wh, wl, 32, n0, tid);
    cp_commit();

    float acc[4][4][4];
#pragma unroll
    for (int i = 0; i < 4; i++)
#pragma unroll
        for (int j = 0; j < 4; j++)
#pragma unroll
            for (int r = 0; r < 4; r++) acc[i][j][r] = 0.f;

    int lane = tid & 31, w = tid >> 5;
    int warpM = w >> 2, warpN = w & 3;
    int p0 = warpN * 32, p1 = warpN * 32 + 16;

    const int NK = IE / 32;  // 16
    for (int ki = 0; ki < NK; ki++) {
        cp_wait1();
        __syncthreads();
        if (ki + 2 < NK)
            g2_load(sb + ((ki + 2) % 3) * STG, m0, rows, wh, wl, (ki + 2) * 32, n0, tid);
        cp_commit();
        uint32_t stb = sb + (ki % 3) * STG;
        compute_k16(stb, lane, warpM, p0, p1, 0, acc);
        compute_k16(stb, lane, warpM, p0, p1, 1, acc);
    }

#pragma unroll
    for (int i = 0; i < 4; i++) {
        int r0 = warpM * 64 + i * 16 + (lane >> 2);
#pragma unroll
        for (int hfa = 0; hfa < 2; hfa++) {
            int m = r0 + hfa * 8;
            if (m < rows) {
                int token = sRow[m];
                float* po = out + (size_t)token * H + n0;
#pragma unroll
                for (int j = 0; j < 4; j++) {
                    int col = warpN * 32 + j * 8 + (lane & 3) * 2;
                    float2 v = make_float2(acc[i][j][hfa * 2 + 0],
                                           acc[i][j][hfa * 2 + 1]);
                    *(float2*)(po + col) = v;
                }
            }
        }
    }
}

// ---------------- launch ----------------
extern "C" void kernel_launch(void* const* d_in, const int* in_sizes, int n_in,
                              void* d_out, int out_size) {
    const float* hs  = (const float*)d_in[0];
    const int*   tok = (const int*)d_in[1];
    const float* mu  = (const float*)d_in[2];
    const float* gup = (const float*)d_in[3];
    const float* dwn = (const float*)d_in[4];
    const float* rw  = (const float*)d_in[5];
    float* out = (float*)d_out;
    (void)in_sizes; (void)n_in; (void)out_size;

    cudaFuncSetAttribute(k_gemm1_mma, cudaFuncAttributeMaxDynamicSharedMemorySize,
                         SMEM_TOT);
    cudaFuncSetAttribute(k_gemm2_mma, cudaFuncAttributeMaxDynamicSharedMemorySize,
                         SMEM_TOT);

    k_init<<<1, 32>>>();
    k_router<<<N_TOK / 8, 256>>>(mu, tok, rw);
    k_plan<<<1, 1>>>();
    k_scatter<<<N_TOK / 256, 256>>>();

    {
        __nv_bfloat16 *xh, *xl, *gh, *gl, *dh, *dl;
        cudaGetSymbolAddress((void**)&xh, g_x_hi);
        cudaGetSymbolAddress((void**)&xl, g_x_lo);
        cudaGetSymbolAddress((void**)&gh, g_gup_hi);
        cudaGetSymbolAddress((void**)&gl, g_gup_lo);
        cudaGetSymbolAddress((void**)&dh, g_dwn_hi);
        cudaGetSymbolAddress((void**)&dl, g_dwn_lo);
        k_split<<<(N_TOK * H / 4 + 255) / 256, 256>>>(hs, xh, xl, N_TOK * H / 4);
        k_split<<<(E * H * F2 / 4 + 255) / 256, 256>>>(gup, gh, gl, E * H * F2 / 4);
        k_split<<<(E * IE * H / 4 + 255) / 256, 256>>>(dwn, dh, dl, E * IE * H / 4);
    }

    k_gemm1_mma<<<dim3(72, 8), 256, SMEM_TOT>>>();
    k_gemm2_mma<<<dim3(72, 8), 256, SMEM_TOT>>>(out);
}